// round 9
// baseline (speedup 1.0000x reference)
#include <cuda_runtime.h>
#include <cstdint>
#include <cstddef>

#define NUM_VARS  512
#define EMBED_DIM 32
#define IN_DIM    512
#define TOP_K     10
#define BATCH     256
#define TI        16                       // rows per tile
#define NITEMS    (BATCH * (NUM_VARS/TI))  // 8192 work items
#define GRID      304

// vbuf layout: row stride = 32 lanes * 20 words (16 used + 4 pad) = 640 floats
#define VROW_STRIDE 640
#define LANE_STRIDE 20

// scratch (no allocations allowed)
__device__ float g_s[BATCH * EMBED_DIM];   // (c*c)[b][e]
__device__ float g_gate[BATCH];            // sigmoid(c@Wg+bg)
__device__ int   g_ready[BATCH];           // publish flags (zero-init; stale-1 on
                                           // replay is benign: g_s is bitwise
                                           // deterministic for fixed inputs)

// --------------------------------------------------------------------------
// smem: ebuf4 [8 ef][512 j] float4 (64 KB)
//       vbuf  [16 rows][640] f32   (40 KB, lane-contiguous, pad 20)
//         (vbuf doubles as ctx-MLP scratch before the tile loop)
//       abuf  [16 rows][16 ep] float2 (2 KB)
//       seen  [256] char
// --------------------------------------------------------------------------
#define SMEM_EBUF_BYTES (8 * NUM_VARS * 16)
#define SMEM_VBUF_BYTES (TI * VROW_STRIDE * 4)
#define SMEM_ABUF_BYTES (TI * 16 * 8)
#define SMEM_TOTAL (SMEM_EBUF_BYTES + SMEM_VBUF_BYTES + SMEM_ABUF_BYTES + BATCH)

// local top-2 (u32-bit order == float order for sigmoid>0); strict '>' keeps
// the smallest index on exact ties, matching jax top_k.
__device__ __forceinline__ void scan_top2(const float* __restrict__ lptr, int base,
                                          unsigned& t1, int& i1,
                                          unsigned& t2, int& i2) {
    t1 = 0u; i1 = base; t2 = 0u; i2 = base;
    #pragma unroll
    for (int cc = 0; cc < 4; ++cc) {
        const float4 vv = reinterpret_cast<const float4*>(lptr)[cc];
        const float va[4] = {vv.x, vv.y, vv.z, vv.w};
        #pragma unroll
        for (int u = 0; u < 4; ++u) {
            const unsigned bx = __float_as_uint(va[u]);
            const int j = base + 4 * cc + u;
            const bool p1 = bx > t1;
            const bool p2 = bx > t2;
            t2 = p1 ? t1 : (p2 ? bx : t2);
            i2 = p1 ? i1 : (p2 ? j  : i2);
            t1 = p1 ? bx : t1;
            i1 = p1 ? j  : i1;
        }
    }
}

__global__ __launch_bounds__(256, 2) void adj_kernel(
    const float* __restrict__ x,     // [256, 512]
    const float* __restrict__ emb,   // [512, 32]
    const float* __restrict__ W1,    // [32, 512]
    const float* __restrict__ b1,    // [32]
    const float* __restrict__ W2,    // [32, 32]
    const float* __restrict__ b2,    // [32]
    const float* __restrict__ Wg,    // [32]
    const float* __restrict__ bg,    // [1]
    float* __restrict__ out)         // [256, 512, 512]
{
    extern __shared__ unsigned char smem_raw[];
    float4* ebuf4 = reinterpret_cast<float4*>(smem_raw);
    float*  vbuf  = reinterpret_cast<float*>(smem_raw + SMEM_EBUF_BYTES);
    float2* abuf2 = reinterpret_cast<float2*>(smem_raw + SMEM_EBUF_BYTES + SMEM_VBUF_BYTES);
    char*   seen  = reinterpret_cast<char*>(smem_raw + SMEM_EBUF_BYTES + SMEM_VBUF_BYTES + SMEM_ABUF_BYTES);
    ulonglong2* ebufU2 = reinterpret_cast<ulonglong2*>(ebuf4);
    ulonglong2* abufU2 = reinterpret_cast<ulonglong2*>(abuf2);

    const int tid = threadIdx.x;
    const int bid = blockIdx.x;

    seen[tid] = 0;   // 256 threads cover BATCH exactly

    // ---- stage emb once: ebuf4[ef][j] = emb[j][4ef..4ef+3] ----
    for (int idx = tid; idx < NUM_VARS * 8; idx += 256) {
        const int j = idx >> 3, ef = idx & 7;
        ebuf4[ef * NUM_VARS + j] = reinterpret_cast<const float4*>(emb)[idx];
    }
    __syncthreads();

    const int w = tid >> 5, l = tid & 31;

    // ---- inline ctx MLP: CTA c (< 256) produces b = c, publishes flag ----
    if (bid < BATCH) {
        float* xs = vbuf;            // 512 floats (vbuf scratch, pre-tile)
        float* hs = vbuf + IN_DIM;   // 32 floats
        const float* xrow = x + (size_t)bid * IN_DIM;
        for (int i = tid; i < IN_DIM; i += 256) xs[i] = xrow[i];
        __syncthreads();

        // h = relu(x@W1^T + b1): warp w computes e in [4w, 4w+4)
        #pragma unroll
        for (int eo = 0; eo < 4; ++eo) {
            const int e = w * 4 + eo;
            const float* wrow = W1 + (size_t)e * IN_DIM;
            float p = 0.f;
            #pragma unroll 4
            for (int k = l; k < IN_DIM; k += 32) p = fmaf(xs[k], wrow[k], p);
            #pragma unroll
            for (int o = 16; o; o >>= 1) p += __shfl_xor_sync(0xffffffffu, p, o);
            if (l == 0) hs[e] = fmaxf(p + b1[e], 0.f);
        }
        __syncthreads();

        if (w == 0) {                // c = h@W2^T + b2, lane = e
            const int e = l;
            float c = b2[e];
            #pragma unroll
            for (int k = 0; k < EMBED_DIM; ++k) c = fmaf(W2[e * EMBED_DIM + k], hs[k], c);
            g_s[bid * EMBED_DIM + e] = c * c;
            float gp = c * Wg[e];
            #pragma unroll
            for (int o = 16; o; o >>= 1) gp += __shfl_xor_sync(0xffffffffu, gp, o);
            if (e == 0) g_gate[bid] = __fdividef(1.f, 1.f + __expf(-(gp + bg[0])));
        }
        __syncthreads();
        if (tid == 0) {
            __threadfence();                 // release g_s/g_gate
            atomicExch(&g_ready[bid], 1);
            seen[bid] = 1;
        }
        __syncthreads();
    }

    const int tj = tid & 63;     // column group (j = tj + 64q)
    const int ti = tid >> 6;     // row group   (i = ti*4 + k)
    const int tjoff = ((tj >> 4) * LANE_STRIDE) + (tj & 15);  // vbuf col offset

    for (int item = bid; item < NITEMS; item += GRID) {
        const int b  = item >> 5;
        const int i0 = (item & 31) * TI;

        // ---- wait for producer of b (once per CTA per b) ----
        if (tid == 0 && !seen[b]) {
            while (*(volatile int*)&g_ready[b] == 0) {}
            __threadfence();                 // acquire
            seen[b] = 1;
        }
        __syncthreads();

        // abuf[i][ep] = emb[i0+i][2ep..2ep+1] * s[b][2ep..2ep+1]
        {
            const int i = tid >> 4, ep = tid & 15;
            float2 ev = reinterpret_cast<const float2*>(emb)[(i0 + i) * 16 + ep];
            float2 sv = reinterpret_cast<const float2*>(g_s + b * EMBED_DIM)[ep];
            ev.x *= sv.x; ev.y *= sv.y;
            abuf2[i * 16 + ep] = ev;
        }
        __syncthreads();

        // ---- main f32x2 FMA loop: 4 rows x 8 cols, float4 (2 e-pairs) steps ----
        unsigned long long acc[4][8];
        #pragma unroll
        for (int i = 0; i < 4; ++i)
            #pragma unroll
            for (int q = 0; q < 8; ++q) acc[i][q] = 0ull;

        #pragma unroll
        for (int ef = 0; ef < 8; ++ef) {
            ulonglong2 av[4];
            #pragma unroll
            for (int i = 0; i < 4; ++i) av[i] = abufU2[(ti * 4 + i) * 8 + ef]; // broadcast
            #pragma unroll
            for (int q = 0; q < 8; ++q) {
                const ulonglong2 bv = ebufU2[ef * NUM_VARS + tj + 64 * q];
                #pragma unroll
                for (int i = 0; i < 4; ++i) {
                    asm("fma.rn.f32x2 %0, %1, %2, %0;"
                        : "+l"(acc[i][q]) : "l"(av[i].x), "l"(bv.x));
                    asm("fma.rn.f32x2 %0, %1, %2, %0;"
                        : "+l"(acc[i][q]) : "l"(av[i].y), "l"(bv.y));
                }
            }
        }

        const float gate = g_gate[b];

        // ---- sigmoid epilogue -> vbuf (lane-contiguous layout) ----
        #pragma unroll
        for (int i = 0; i < 4; ++i) {
            #pragma unroll
            for (int q = 0; q < 8; ++q) {
                const float lo = __uint_as_float((unsigned)acc[i][q]);
                const float hi = __uint_as_float((unsigned)(acc[i][q] >> 32));
                const float xv = lo + hi;
                const float v  = __fdividef(1.f, 1.f + __expf(-xv));
                vbuf[(ti * 4 + i) * VROW_STRIDE + q * (4 * LANE_STRIDE) + tjoff] = v;
            }
        }
        __syncthreads();

        // ---- exact top-10: warp w owns rows 2w, 2w+1; both interleaved ----
        {
            const int ra = 2 * w, rb = 2 * w + 1;
            float* rowa = out + ((size_t)b * NUM_VARS + (i0 + ra)) * NUM_VARS;
            float* rowb = rowa + NUM_VARS;
            const float* lpa = vbuf + ra * VROW_STRIDE + l * LANE_STRIDE;
            const float* lpb = lpa + VROW_STRIDE;
            const int base = l * 16;

            // zero both output rows (coalesced float4)
            const float4 z = make_float4(0.f, 0.f, 0.f, 0.f);
            #pragma unroll
            for (int c = 0; c < 4; ++c) {
                reinterpret_cast<float4*>(rowa)[c * 32 + l] = z;
                reinterpret_cast<float4*>(rowb)[c * 32 + l] = z;
            }

            unsigned t1a, t2a, t1b, t2b; int i1a, i2a, i1b, i2b;
            scan_top2(lpa, base, t1a, i1a, t2a, i2a);
            scan_top2(lpb, base, t1b, i1b, t2b, i2b);
            bool h2a = true, h2b = true;
            __syncwarp();   // order zero-stores before winner stores

            #pragma unroll 1
            for (int it = 0; it < TOP_K; ++it) {
                unsigned wm0, wm1;
                asm("redux.sync.max.u32 %0, %1, 0xffffffff;" : "=r"(wm0) : "r"(t1a));
                asm("redux.sync.max.u32 %0, %1, 0xffffffff;" : "=r"(wm1) : "r"(t1b));
                const unsigned ba = __ballot_sync(0xffffffffu, t1a == wm0);
                const unsigned bb = __ballot_sync(0xffffffffu, t1b == wm1);
                if (l == __ffs(ba) - 1) {            // min index on ties
                    rowa[i1a] = __uint_as_float(wm0) * gate;
                    *(float*)(lpa + (i1a & 15)) = 0.f;   // remove from vbuf
                    if (it < TOP_K - 1) {
                        if (h2a) { t1a = t2a; i1a = i2a; h2a = false; }
                        else     { scan_top2(lpa, base, t1a, i1a, t2a, i2a); h2a = true; }
                    }
                }
                if (l == __ffs(bb) - 1) {
                    rowb[i1b] = __uint_as_float(wm1) * gate;
                    *(float*)(lpb + (i1b & 15)) = 0.f;
                    if (it < TOP_K - 1) {
                        if (h2b) { t1b = t2b; i1b = i2b; h2b = false; }
                        else     { scan_top2(lpb, base, t1b, i1b, t2b, i2b); h2b = true; }
                    }
                }
            }
        }
        __syncthreads();   // vbuf/abuf reuse barrier
    }
}

// --------------------------------------------------------------------------
extern "C" void kernel_launch(void* const* d_in, const int* in_sizes, int n_in,
                              void* d_out, int out_size) {
    const float* ctx = (const float*)d_in[0];  // [256,512]
    const float* emb = (const float*)d_in[1];  // [512,32]
    const float* W1  = (const float*)d_in[2];  // [32,512]
    const float* b1  = (const float*)d_in[3];  // [32]
    const float* W2  = (const float*)d_in[4];  // [32,32]
    const float* b2  = (const float*)d_in[5];  // [32]
    const float* Wg  = (const float*)d_in[6];  // [1,32]
    const float* bg  = (const float*)d_in[7];  // [1]
    float* out = (float*)d_out;

    cudaFuncSetAttribute(adj_kernel,
                         cudaFuncAttributeMaxDynamicSharedMemorySize, SMEM_TOTAL);
    adj_kernel<<<GRID, 256, SMEM_TOTAL>>>(ctx, emb, W1, b1, W2, b2, Wg, bg, out);
}

// round 10
// speedup vs baseline: 1.6101x; 1.6101x over previous
#include <cuda_runtime.h>
#include <cstdint>
#include <cstddef>

#define NUM_VARS  512
#define EMBED_DIM 32
#define IN_DIM    512
#define TOP_K     10
#define BATCH     256
#define TI        16                       // rows per tile
#define NITEMS    (BATCH * (NUM_VARS/TI))  // 8192 work items
#define GRID      304

// vbuf layout: row stride = 32 lanes * 20 words (16 used + 4 pad) = 640 floats
#define VROW_STRIDE 640
#define LANE_STRIDE 20

// scratch (no allocations allowed)
__device__ float g_s[BATCH * EMBED_DIM];   // (c*c)[b][e]
__device__ float g_gate[BATCH];            // sigmoid(c@Wg+bg)

// --------------------------------------------------------------------------
// Kernel A: context MLP -> c, s=c^2, gate. One block per batch row.
// --------------------------------------------------------------------------
__global__ __launch_bounds__(128) void ctx_kernel(
    const float* __restrict__ x,    // [B, 512]
    const float* __restrict__ W1,   // [32, 512]
    const float* __restrict__ b1,   // [32]
    const float* __restrict__ W2,   // [32, 32]
    const float* __restrict__ b2,   // [32]
    const float* __restrict__ Wg,   // [32]
    const float* __restrict__ bg)   // [1]
{
    __shared__ float xs[IN_DIM];
    __shared__ float hs[EMBED_DIM];
    const int b   = blockIdx.x;
    const int tid = threadIdx.x;
    const float* xrow = x + (size_t)b * IN_DIM;
    for (int i = tid; i < IN_DIM; i += 128) xs[i] = xrow[i];
    __syncthreads();

    const int w = tid >> 5, l = tid & 31;
    for (int eo = 0; eo < 8; ++eo) {
        const int e = w * 8 + eo;
        const float* wrow = W1 + (size_t)e * IN_DIM;
        float p = 0.f;
        #pragma unroll 4
        for (int k = l; k < IN_DIM; k += 32) p = fmaf(xs[k], wrow[k], p);
        #pragma unroll
        for (int o = 16; o; o >>= 1) p += __shfl_xor_sync(0xffffffffu, p, o);
        if (l == 0) hs[e] = fmaxf(p + b1[e], 0.f);
    }
    __syncthreads();

    if (w == 0) {
        const int e = l;
        float c = b2[e];
        #pragma unroll
        for (int k = 0; k < EMBED_DIM; ++k) c = fmaf(W2[e * EMBED_DIM + k], hs[k], c);
        g_s[b * EMBED_DIM + e] = c * c;
        float gp = c * Wg[e];
        #pragma unroll
        for (int o = 16; o; o >>= 1) gp += __shfl_xor_sync(0xffffffffu, gp, o);
        if (e == 0) g_gate[b] = __fdividef(1.f, 1.f + __expf(-(gp + bg[0])));
    }
}

// --------------------------------------------------------------------------
// Kernel B: persistent adj + sigmoid + exact top-k + gated write.
// smem: ebuf4 [8 ef][512 j] float4 (64 KB)
//       vbuf  [16 rows][640] f32   (40 KB, lane-contiguous, pad 20)
//       abuf  [16 rows][16 ep] float2 (2 KB)
// --------------------------------------------------------------------------
#define SMEM_EBUF_BYTES (8 * NUM_VARS * 16)
#define SMEM_VBUF_BYTES (TI * VROW_STRIDE * 4)
#define SMEM_ABUF_BYTES (TI * 16 * 8)
#define SMEM_TOTAL (SMEM_EBUF_BYTES + SMEM_VBUF_BYTES + SMEM_ABUF_BYTES)

// local top-2 over the lane's 16 owned slots (u32-bit order == float order for
// sigmoid>0); strict '>' keeps the smallest index on ties, matching jax top_k.
__device__ __forceinline__ void scan_top2(const float* __restrict__ lptr, int base,
                                          unsigned& t1, int& i1,
                                          unsigned& t2, int& i2) {
    t1 = 0u; i1 = base; t2 = 0u; i2 = base;
    #pragma unroll
    for (int cc = 0; cc < 4; ++cc) {
        const float4 vv = reinterpret_cast<const float4*>(lptr)[cc];
        const float va[4] = {vv.x, vv.y, vv.z, vv.w};
        #pragma unroll
        for (int u = 0; u < 4; ++u) {
            const unsigned bx = __float_as_uint(va[u]);
            const int j = base + 4 * cc + u;
            const bool p1 = bx > t1;
            const bool p2 = bx > t2;
            t2 = p1 ? t1 : (p2 ? bx : t2);
            i2 = p1 ? i1 : (p2 ? j  : i2);
            t1 = p1 ? bx : t1;
            i1 = p1 ? j  : i1;
        }
    }
}

__global__ __launch_bounds__(256, 2) void adj_kernel(
    const float* __restrict__ emb,   // [512, 32]
    float* __restrict__ out)         // [256, 512, 512]
{
    extern __shared__ unsigned char smem_raw[];
    float4* ebuf4 = reinterpret_cast<float4*>(smem_raw);
    float*  vbuf  = reinterpret_cast<float*>(smem_raw + SMEM_EBUF_BYTES);
    float2* abuf2 = reinterpret_cast<float2*>(smem_raw + SMEM_EBUF_BYTES + SMEM_VBUF_BYTES);
    ulonglong2* ebufU2 = reinterpret_cast<ulonglong2*>(ebuf4);
    ulonglong2* abufU2 = reinterpret_cast<ulonglong2*>(abuf2);

    const int tid = threadIdx.x;

    // Stage emb once: ebuf4[ef][j] = emb[j][4ef..4ef+3]
    for (int idx = tid; idx < NUM_VARS * 8; idx += 256) {
        const int j = idx >> 3, ef = idx & 7;
        ebuf4[ef * NUM_VARS + j] = reinterpret_cast<const float4*>(emb)[idx];
    }
    __syncthreads();

    const int tj = tid & 63;     // column group (j = tj + 64q)
    const int ti = tid >> 6;     // row group   (i = ti*4 + k)
    const int w  = tid >> 5, l = tid & 31;
    const int tjoff = ((tj >> 4) * LANE_STRIDE) + (tj & 15);  // vbuf col offset

    for (int item = blockIdx.x; item < NITEMS; item += GRID) {
        const int b  = item >> 5;
        const int i0 = (item & 31) * TI;

        // abuf[i][ep] = emb[i0+i][2ep..2ep+1] * s[b][2ep..2ep+1]
        {
            const int i = tid >> 4, ep = tid & 15;
            float2 ev = reinterpret_cast<const float2*>(emb)[(i0 + i) * 16 + ep];
            float2 sv = reinterpret_cast<const float2*>(g_s + b * EMBED_DIM)[ep];
            ev.x *= sv.x; ev.y *= sv.y;
            abuf2[i * 16 + ep] = ev;
        }
        __syncthreads();

        // ---- main f32x2 FMA loop: 4 rows x 8 cols, float4 (2 e-pairs) steps ----
        unsigned long long acc[4][8];
        #pragma unroll
        for (int i = 0; i < 4; ++i)
            #pragma unroll
            for (int q = 0; q < 8; ++q) acc[i][q] = 0ull;

        #pragma unroll
        for (int ef = 0; ef < 8; ++ef) {
            ulonglong2 av[4];
            #pragma unroll
            for (int i = 0; i < 4; ++i) av[i] = abufU2[(ti * 4 + i) * 8 + ef]; // broadcast
            #pragma unroll
            for (int q = 0; q < 8; ++q) {
                const ulonglong2 bv = ebufU2[ef * NUM_VARS + tj + 64 * q];
                #pragma unroll
                for (int i = 0; i < 4; ++i) {
                    asm("fma.rn.f32x2 %0, %1, %2, %0;"
                        : "+l"(acc[i][q]) : "l"(av[i].x), "l"(bv.x));
                    asm("fma.rn.f32x2 %0, %1, %2, %0;"
                        : "+l"(acc[i][q]) : "l"(av[i].y), "l"(bv.y));
                }
            }
        }

        const float gate = g_gate[b];

        // ---- sigmoid epilogue -> vbuf (lane-contiguous layout) ----
        #pragma unroll
        for (int i = 0; i < 4; ++i) {
            #pragma unroll
            for (int q = 0; q < 8; ++q) {
                const float lo = __uint_as_float((unsigned)acc[i][q]);
                const float hi = __uint_as_float((unsigned)(acc[i][q] >> 32));
                const float xv = lo + hi;
                const float v  = __fdividef(1.f, 1.f + __expf(-xv));
                vbuf[(ti * 4 + i) * VROW_STRIDE + q * (4 * LANE_STRIDE) + tjoff] = v;
            }
        }
        __syncthreads();

        // ---- exact top-10: warp w owns rows 2w, 2w+1, interleaved ----
        {
            const int ra = 2 * w, rb = 2 * w + 1;
            float* rowa = out + ((size_t)b * NUM_VARS + (i0 + ra)) * NUM_VARS;
            float* rowb = rowa + NUM_VARS;
            const float* lpa = vbuf + ra * VROW_STRIDE + l * LANE_STRIDE;
            const float* lpb = lpa + VROW_STRIDE;
            const int base = l * 16;

            // zero both output rows (coalesced float4)
            const float4 z = make_float4(0.f, 0.f, 0.f, 0.f);
            #pragma unroll
            for (int c = 0; c < 4; ++c) {
                reinterpret_cast<float4*>(rowa)[c * 32 + l] = z;
                reinterpret_cast<float4*>(rowb)[c * 32 + l] = z;
            }

            unsigned t1a, t2a, t1b, t2b; int i1a, i2a, i1b, i2b;
            scan_top2(lpa, base, t1a, i1a, t2a, i2a);
            scan_top2(lpb, base, t1b, i1b, t2b, i2b);
            bool h2a = true, h2b = true;
            __syncwarp();   // order zero-stores before winner stores

            #pragma unroll 1
            for (int it = 0; it < TOP_K; ++it) {
                unsigned wm0, wm1;
                asm("redux.sync.max.u32 %0, %1, 0xffffffff;" : "=r"(wm0) : "r"(t1a));
                asm("redux.sync.max.u32 %0, %1, 0xffffffff;" : "=r"(wm1) : "r"(t1b));
                const unsigned ba = __ballot_sync(0xffffffffu, t1a == wm0);
                const unsigned bb = __ballot_sync(0xffffffffu, t1b == wm1);
                if (l == __ffs(ba) - 1) {            // min index on ties
                    rowa[i1a] = __uint_as_float(wm0) * gate;
                    *(float*)(lpa + (i1a & 15)) = 0.f;   // remove (bits 0)
                    if (it < TOP_K - 1) {
                        if (h2a) { t1a = t2a; i1a = i2a; h2a = false; }
                        else     { scan_top2(lpa, base, t1a, i1a, t2a, i2a); h2a = true; }
                    }
                }
                if (l == __ffs(bb) - 1) {
                    rowb[i1b] = __uint_as_float(wm1) * gate;
                    *(float*)(lpb + (i1b & 15)) = 0.f;
                    if (it < TOP_K - 1) {
                        if (h2b) { t1b = t2b; i1b = i2b; h2b = false; }
                        else     { scan_top2(lpb, base, t1b, i1b, t2b, i2b); h2b = true; }
                    }
                }
                // no __syncwarp needed: lanes touch only their own vbuf slots;
                // redux/ballot reconverge the warp each iteration.
            }
        }
        __syncthreads();   // vbuf/abuf reuse barrier
    }
}

// --------------------------------------------------------------------------
extern "C" void kernel_launch(void* const* d_in, const int* in_sizes, int n_in,
                              void* d_out, int out_size) {
    const float* ctx = (const float*)d_in[0];  // [256,512]
    const float* emb = (const float*)d_in[1];  // [512,32]
    const float* W1  = (const float*)d_in[2];  // [32,512]
    const float* b1  = (const float*)d_in[3];  // [32]
    const float* W2  = (const float*)d_in[4];  // [32,32]
    const float* b2  = (const float*)d_in[5];  // [32]
    const float* Wg  = (const float*)d_in[6];  // [1,32]
    const float* bg  = (const float*)d_in[7];  // [1]
    float* out = (float*)d_out;

    ctx_kernel<<<BATCH, 128>>>(ctx, W1, b1, W2, b2, Wg, bg);

    cudaFuncSetAttribute(adj_kernel,
                         cudaFuncAttributeMaxDynamicSharedMemorySize, SMEM_TOTAL);
    adj_kernel<<<GRID, 256, SMEM_TOTAL>>>(emb, out);
}